// round 2
// baseline (speedup 1.0000x reference)
#include <cuda_runtime.h>
#include <math.h>

#define S_LEN 512
#define HD    64
#define NH    16
#define NB    8
#define BH    128          // NB*NH
#define DIM   1024
#define POSJ  1024
#define SCORE_SCALE 0.07216878364870322f   // 1/sqrt(64*3)

// ---------------- scratch (static device globals; no runtime allocation) ----
__device__ float g_q[BH * S_LEN * HD];           // [b,h,s,d]
__device__ float g_k[BH * S_LEN * HD];
__device__ float g_v[BH * S_LEN * HD];
__device__ float g_posq[NH * POSJ * HD];         // [h,j,d]
__device__ float g_posk[NH * POSJ * HD];
__device__ float g_c2p[(size_t)BH * S_LEN * S_LEN];  // [bh][q][k]
__device__ float g_p2c[(size_t)BH * S_LEN * S_LEN];  // [bh][k][q]

// ---------------------------------------------------------------------------
// Projection GEMM: C[m,n] = sum_k A[m,k] * W[n,k] + bias[n]
// MODE 0: token store into [b,h,s,d]; MODE 1: pos store into [h,j,d]
// DST selects destination scratch array.
// Tiles: BM=BN=64, BK=16, 256 threads, 4x4 microtile.
// ---------------------------------------------------------------------------
template <int MODE, int DST>
__global__ void __launch_bounds__(256) proj_kernel(const float* __restrict__ A,
                                                   const float* __restrict__ W,
                                                   const float* __restrict__ bias)
{
    float* out = (DST == 0) ? g_q : (DST == 1) ? g_k : (DST == 2) ? g_v
               : (DST == 3) ? g_posq : g_posk;

    __shared__ float As[16][64];
    __shared__ float Bs[16][64];

    const int tid = threadIdx.x;
    const int bm = blockIdx.y, bn = blockIdx.x;
    const int ty = tid >> 4, tx = tid & 15;
    const int lr = tid >> 2;             // 0..63
    const int lc = (tid & 3) << 2;       // 0,4,8,12

    const float* Ap = A + (size_t)(bm * 64 + lr) * DIM + lc;
    const float* Wp = W + (size_t)(bn * 64 + lr) * DIM + lc;

    float acc[4][4] = {};
    for (int kt = 0; kt < DIM; kt += 16) {
        float4 av = *(const float4*)(Ap + kt);
        float4 wv = *(const float4*)(Wp + kt);
        __syncthreads();
        As[lc + 0][lr] = av.x; As[lc + 1][lr] = av.y;
        As[lc + 2][lr] = av.z; As[lc + 3][lr] = av.w;
        Bs[lc + 0][lr] = wv.x; Bs[lc + 1][lr] = wv.y;
        Bs[lc + 2][lr] = wv.z; Bs[lc + 3][lr] = wv.w;
        __syncthreads();
#pragma unroll
        for (int kk = 0; kk < 16; kk++) {
            const float4 a4 = *(const float4*)&As[kk][ty << 2];
            const float4 b4 = *(const float4*)&Bs[kk][tx << 2];
            const float a[4] = {a4.x, a4.y, a4.z, a4.w};
            const float b[4] = {b4.x, b4.y, b4.z, b4.w};
#pragma unroll
            for (int i = 0; i < 4; i++)
#pragma unroll
                for (int j = 0; j < 4; j++)
                    acc[i][j] = fmaf(a[i], b[j], acc[i][j]);
        }
    }

#pragma unroll
    for (int i = 0; i < 4; i++) {
        const int m = bm * 64 + (ty << 2) + i;
#pragma unroll
        for (int j = 0; j < 4; j++) {
            const int n = bn * 64 + (tx << 2) + j;
            const float v = acc[i][j] + bias[n];
            if (MODE == 0) {
                // token t=m -> b=m>>9, s=m&511 ; feature n -> h=n>>6, d=n&63
                out[((size_t)((m >> 9) * NH + (n >> 6)) * S_LEN + (m & 511)) * HD + (n & 63)] = v;
            } else {
                out[((size_t)(n >> 6) * POSJ + m) * HD + (n & 63)] = v;
            }
        }
    }
}

// ---------------------------------------------------------------------------
// Banded relative-attention GEMMs with gathered epilogue.
// MODE 0 (c2p): A=Q[bh] [512,64], B=posK[h] [1024,64].
//   elem (m=q, n=j): k = m - n + 512; if 0<=k<512: g_c2p[bh][m][k] = acc
// MODE 1 (p2c): A=K[bh] [512,64], B=posQ[h] [1024,64].
//   elem (m=k, n=j): q = m + n - 512; if 0<=q<512: g_p2c[bh][m][q] = acc
// Both stores are contiguous in the last index across the thread's j's.
// ---------------------------------------------------------------------------
template <int MODE>
__global__ void __launch_bounds__(256) rel_kernel()
{
    __shared__ float As[16][64];
    __shared__ float Bs[16][64];

    const int tid = threadIdx.x;
    const int bn = blockIdx.x, bm = blockIdx.y, bh = blockIdx.z;
    const int h = bh & (NH - 1);

    const float* A  = (MODE == 0 ? g_q : g_k) + (size_t)bh * S_LEN * HD;
    const float* Bm = (MODE == 0 ? g_posk : g_posq) + (size_t)h * POSJ * HD;
    float* out      = (MODE == 0 ? g_c2p : g_p2c) + (size_t)bh * S_LEN * S_LEN;

    const int ty = tid >> 4, tx = tid & 15;
    const int lr = tid >> 2, lc = (tid & 3) << 2;

    const float* Ap = A + (size_t)(bm * 64 + lr) * HD + lc;
    const float* Bp = Bm + (size_t)(bn * 64 + lr) * HD + lc;

    float acc[4][4] = {};
#pragma unroll
    for (int kt = 0; kt < HD; kt += 16) {
        float4 av = *(const float4*)(Ap + kt);
        float4 bv = *(const float4*)(Bp + kt);
        __syncthreads();
        As[lc + 0][lr] = av.x; As[lc + 1][lr] = av.y;
        As[lc + 2][lr] = av.z; As[lc + 3][lr] = av.w;
        Bs[lc + 0][lr] = bv.x; Bs[lc + 1][lr] = bv.y;
        Bs[lc + 2][lr] = bv.z; Bs[lc + 3][lr] = bv.w;
        __syncthreads();
#pragma unroll
        for (int kk = 0; kk < 16; kk++) {
            const float4 a4 = *(const float4*)&As[kk][ty << 2];
            const float4 b4 = *(const float4*)&Bs[kk][tx << 2];
            const float a[4] = {a4.x, a4.y, a4.z, a4.w};
            const float b[4] = {b4.x, b4.y, b4.z, b4.w};
#pragma unroll
            for (int i = 0; i < 4; i++)
#pragma unroll
                for (int j = 0; j < 4; j++)
                    acc[i][j] = fmaf(a[i], b[j], acc[i][j]);
        }
    }

#pragma unroll
    for (int i = 0; i < 4; i++) {
        const int m = bm * 64 + (ty << 2) + i;
#pragma unroll
        for (int j = 0; j < 4; j++) {
            const int n = bn * 64 + (tx << 2) + j;
            if (MODE == 0) {
                const int k = m - n + 512;
                if ((unsigned)k < S_LEN) out[(size_t)m * S_LEN + k] = acc[i][j];
            } else {
                const int q = m + n - 512;
                if ((unsigned)q < S_LEN) out[(size_t)m * S_LEN + q] = acc[i][j];
            }
        }
    }
}

// ---------------------------------------------------------------------------
// Fused attention. One CTA per (bh, q-tile of 64). k-tiles of 64, online
// softmax, PV accumulate. Buffers:
//   QsT [64][64] : Q transposed [d][q]       (persistent)
//   BufK[64][64] : KsT [d][k] during S, Vs [k][d] during PV
//   BufP[64][68] : p2c tile [k][q] during S, P (exp) tile [k][q] during PV
// c2p is read straight from gmem (coalesced, [q][k] layout).
// ---------------------------------------------------------------------------
#define ATTN_SMEM_BYTES ((64 * 64 + 64 * 64 + 64 * 68) * 4)

__global__ void __launch_bounds__(256) attn_kernel(const float* __restrict__ mask,
                                                   float* __restrict__ out)
{
    extern __shared__ float sm[];
    float* QsT  = sm;                  // stride 64
    float* BufK = sm + 64 * 64;        // stride 64
    float* BufP = sm + 2 * 64 * 64;    // stride 68

    const int tid = threadIdx.x;
    const int bh = blockIdx.y;
    const int b = bh >> 4, h = bh & 15;
    const int q0 = blockIdx.x << 6;
    const int ty = tid >> 4, tx = tid & 15;

    // load Q tile transposed
#pragma unroll
    for (int r = 0; r < 4; r++) {
        const int idx = tid + r * 256;
        const int row = idx >> 4, c = (idx & 15) << 2;
        float4 v = *(const float4*)(g_q + ((size_t)bh * S_LEN + q0 + row) * HD + c);
        QsT[(c + 0) * 64 + row] = v.x; QsT[(c + 1) * 64 + row] = v.y;
        QsT[(c + 2) * 64 + row] = v.z; QsT[(c + 3) * 64 + row] = v.w;
    }

    float m_i[4], l_i[4], acc[4][4];
#pragma unroll
    for (int i = 0; i < 4; i++) {
        m_i[i] = -1e30f; l_i[i] = 0.f;
#pragma unroll
        for (int j = 0; j < 4; j++) acc[i][j] = 0.f;
    }

    for (int kt = 0; kt < 8; kt++) {
        const int k0 = kt << 6;
        __syncthreads();   // protect QsT (kt=0) and BufK/BufP reuse
        // load K (transposed) and p2c tile
#pragma unroll
        for (int r = 0; r < 4; r++) {
            const int idx = tid + r * 256;
            const int row = idx >> 4, c = (idx & 15) << 2;
            float4 kv = *(const float4*)(g_k + ((size_t)bh * S_LEN + k0 + row) * HD + c);
            BufK[(c + 0) * 64 + row] = kv.x; BufK[(c + 1) * 64 + row] = kv.y;
            BufK[(c + 2) * 64 + row] = kv.z; BufK[(c + 3) * 64 + row] = kv.w;
            float4 pv = *(const float4*)(g_p2c + ((size_t)bh * S_LEN + k0 + row) * S_LEN + q0 + c);
            *(float4*)&BufP[row * 68 + c] = pv;
        }
        __syncthreads();

        // ---- scores: p2c (smem) + c2p (gmem) + QK^T (smem GEMM) -----------
        float s[4][4];
#pragma unroll
        for (int j = 0; j < 4; j++) {
            const float4 pv = *(const float4*)&BufP[((tx << 2) + j) * 68 + (ty << 2)];
            s[0][j] = pv.x; s[1][j] = pv.y; s[2][j] = pv.z; s[3][j] = pv.w;
        }
#pragma unroll
        for (int i = 0; i < 4; i++) {
            const float4 c4 = *(const float4*)(g_c2p +
                ((size_t)bh * S_LEN + q0 + (ty << 2) + i) * S_LEN + k0 + (tx << 2));
            s[i][0] += c4.x; s[i][1] += c4.y; s[i][2] += c4.z; s[i][3] += c4.w;
        }
#pragma unroll
        for (int d = 0; d < 64; d++) {
            const float4 a4 = *(const float4*)&QsT[d * 64 + (ty << 2)];
            const float4 b4 = *(const float4*)&BufK[d * 64 + (tx << 2)];
            const float a[4] = {a4.x, a4.y, a4.z, a4.w};
            const float bb[4] = {b4.x, b4.y, b4.z, b4.w};
#pragma unroll
            for (int i = 0; i < 4; i++)
#pragma unroll
                for (int j = 0; j < 4; j++)
                    s[i][j] = fmaf(a[i], bb[j], s[i][j]);
        }
        const float4 mv = *(const float4*)(mask + b * S_LEN + k0 + (tx << 2));
        const float mk[4] = {mv.x, mv.y, mv.z, mv.w};
#pragma unroll
        for (int i = 0; i < 4; i++)
#pragma unroll
            for (int j = 0; j < 4; j++)
                s[i][j] = s[i][j] * SCORE_SCALE + mk[j];

        __syncthreads();   // everyone done reading BufK(K) / BufP(p2c)

        // ---- online softmax; write P into BufP ----------------------------
#pragma unroll
        for (int i = 0; i < 4; i++) {
            float rm = fmaxf(fmaxf(s[i][0], s[i][1]), fmaxf(s[i][2], s[i][3]));
#pragma unroll
            for (int o = 8; o >= 1; o >>= 1)
                rm = fmaxf(rm, __shfl_xor_sync(0xffffffffu, rm, o));
            const float mn = fmaxf(m_i[i], rm);
            const float sc = __expf(m_i[i] - mn);
            float rs = 0.f;
#pragma unroll
            for (int j = 0; j < 4; j++) {
                const float p = __expf(s[i][j] - mn);
                rs += p;
                BufP[((tx << 2) + j) * 68 + (ty << 2) + i] = p;
            }
#pragma unroll
            for (int o = 8; o >= 1; o >>= 1)
                rs += __shfl_xor_sync(0xffffffffu, rs, o);
            l_i[i] = l_i[i] * sc + rs;
            m_i[i] = mn;
#pragma unroll
            for (int j = 0; j < 4; j++) acc[i][j] *= sc;
        }
        // load V into BufK (natural [k][d])
#pragma unroll
        for (int r = 0; r < 4; r++) {
            const int idx = tid + r * 256;
            const int row = idx >> 4, c = (idx & 15) << 2;
            float4 vv = *(const float4*)(g_v + ((size_t)bh * S_LEN + k0 + row) * HD + c);
            *(float4*)&BufK[row * 64 + c] = vv;
        }
        __syncthreads();

        // ---- PV -----------------------------------------------------------
#pragma unroll
        for (int k = 0; k < 64; k++) {
            const float4 p4 = *(const float4*)&BufP[k * 68 + (ty << 2)];
            const float4 v4 = *(const float4*)&BufK[k * 64 + (tx << 2)];
            const float p[4] = {p4.x, p4.y, p4.z, p4.w};
            const float vv[4] = {v4.x, v4.y, v4.z, v4.w};
#pragma unroll
            for (int i = 0; i < 4; i++)
#pragma unroll
                for (int j = 0; j < 4; j++)
                    acc[i][j] = fmaf(p[i], vv[j], acc[i][j]);
        }
    }

    // epilogue: normalize and write [b, s, h*64+d]
#pragma unroll
    for (int i = 0; i < 4; i++) {
        const float inv = 1.0f / l_i[i];
        const int q = q0 + (ty << 2) + i;
        float4 o;
        o.x = acc[i][0] * inv; o.y = acc[i][1] * inv;
        o.z = acc[i][2] * inv; o.w = acc[i][3] * inv;
        *(float4*)(out + ((size_t)b * S_LEN + q) * DIM + h * HD + (tx << 2)) = o;
    }
}

// ---------------------------------------------------------------------------
extern "C" void kernel_launch(void* const* d_in, const int* in_sizes, int n_in,
                              void* d_out, int out_size)
{
    const float* x    = (const float*)d_in[0];
    const float* rel  = (const float*)d_in[1];
    const float* mask = (const float*)d_in[2];
    const float* Wq   = (const float*)d_in[3];
    const float* bq   = (const float*)d_in[4];
    const float* Wk   = (const float*)d_in[5];
    const float* bk   = (const float*)d_in[6];
    const float* Wv   = (const float*)d_in[7];
    const float* bv   = (const float*)d_in[8];
    float* out = (float*)d_out;

    const dim3 blk(256);

    // projections: Q, K, V from x; posQ, posK from rel_embeddings
    proj_kernel<0, 0><<<dim3(16, 64), blk>>>(x, Wq, bq);
    proj_kernel<0, 1><<<dim3(16, 64), blk>>>(x, Wk, bk);
    proj_kernel<0, 2><<<dim3(16, 64), blk>>>(x, Wv, bv);
    proj_kernel<1, 3><<<dim3(16, 16), blk>>>(rel, Wq, bq);
    proj_kernel<1, 4><<<dim3(16, 16), blk>>>(rel, Wk, bk);

    // banded relative-position GEMMs (gathered epilogue)
    rel_kernel<0><<<dim3(16, 8, BH), blk>>>();
    rel_kernel<1><<<dim3(16, 8, BH), blk>>>();

    // fused attention
    cudaFuncSetAttribute(attn_kernel, cudaFuncAttributeMaxDynamicSharedMemorySize,
                         ATTN_SMEM_BYTES);
    attn_kernel<<<dim3(8, BH), blk, ATTN_SMEM_BYTES>>>(mask, out);
}

// round 3
// speedup vs baseline: 2.0677x; 2.0677x over previous
#include <cuda_runtime.h>
#include <math.h>
#include <stdint.h>

#define S_LEN 512
#define HD    64
#define NH    16
#define NB    8
#define BH    128          // NB*NH
#define DIM   1024
#define POSJ  1024
#define SCORE_SCALE 0.07216878364870322f   // 1/sqrt(64*3)
#define PAD   20           // smem row pitch (u32) — conflict-free for mma frags

// ---------------- scratch (static device globals; no runtime allocation) ----
__device__ float g_q[BH * S_LEN * HD];           // [b,h,s,d]
__device__ float g_k[BH * S_LEN * HD];
__device__ float g_v[BH * S_LEN * HD];
__device__ float g_posq[NH * POSJ * HD];         // [h,j,d]
__device__ float g_posk[NH * POSJ * HD];
__device__ float g_c2p[(size_t)BH * S_LEN * S_LEN];  // [bh][q][k]
__device__ float g_p2c[(size_t)BH * S_LEN * S_LEN];  // [bh][k][q]

// ---------------------------------------------------------------------------
// tf32 helpers
// ---------------------------------------------------------------------------
__device__ __forceinline__ uint32_t f2t(float x) {
    uint32_t u; asm("cvt.rna.tf32.f32 %0, %1;" : "=r"(u) : "f"(x)); return u;
}
__device__ __forceinline__ void st4t(uint32_t* p, float4 v) {
    uint4 u; u.x = f2t(v.x); u.y = f2t(v.y); u.z = f2t(v.z); u.w = f2t(v.w);
    *(uint4*)p = u;
}
__device__ __forceinline__ void mma_tf32(float4& c, const uint32_t* a, const uint32_t* b) {
    asm volatile(
        "mma.sync.aligned.m16n8k8.row.col.f32.tf32.tf32.f32 "
        "{%0,%1,%2,%3}, {%4,%5,%6,%7}, {%8,%9}, {%0,%1,%2,%3};\n"
        : "+f"(c.x), "+f"(c.y), "+f"(c.z), "+f"(c.w)
        : "r"(a[0]), "r"(a[1]), "r"(a[2]), "r"(a[3]), "r"(b[0]), "r"(b[1]));
}

// ---------------------------------------------------------------------------
// tf32 projection GEMM: C[m,n] = sum_k A[m,k] * W[n,k] + bias[n]
// Block tile 128x128, BK=16, 256 threads = 8 warps (4m x 2n), warp tile 32x64.
// MODE 0: store to [b,h,s,d]; MODE 1: store to [h,j,d].
// ---------------------------------------------------------------------------
template <int MODE, int DST>
__global__ void __launch_bounds__(256) proj_tf32(const float* __restrict__ A,
                                                 const float* __restrict__ W,
                                                 const float* __restrict__ bias)
{
    float* out = (DST == 0) ? g_q : (DST == 1) ? g_k : (DST == 2) ? g_v
               : (DST == 3) ? g_posq : g_posk;

    __shared__ uint32_t Asm[128 * PAD];
    __shared__ uint32_t Bsm[128 * PAD];

    const int tid  = threadIdx.x;
    const int warp = tid >> 5, lane = tid & 31;
    const int wm = warp >> 1, wn = warp & 1;
    const int g  = lane >> 2, tg = lane & 3;
    const int bm = blockIdx.y, bn = blockIdx.x;

    const int lrow = tid >> 2;          // 0..63
    const int lc4  = (tid & 3) << 2;    // 0,4,8,12

    const float* Ap = A + (size_t)(bm * 128 + lrow) * DIM + lc4;
    const float* Wp = W + (size_t)(bn * 128 + lrow) * DIM + lc4;

    float4 ar0 = *(const float4*)(Ap);
    float4 ar1 = *(const float4*)(Ap + (size_t)64 * DIM);
    float4 br0 = *(const float4*)(Wp);
    float4 br1 = *(const float4*)(Wp + (size_t)64 * DIM);

    float4 c[2][8];
#pragma unroll
    for (int t = 0; t < 2; t++)
#pragma unroll
        for (int n = 0; n < 8; n++) c[t][n] = make_float4(0.f, 0.f, 0.f, 0.f);

    for (int kt = 0; kt < DIM; kt += 16) {
        __syncthreads();
        st4t(Asm + lrow * PAD + lc4, ar0);
        st4t(Asm + (lrow + 64) * PAD + lc4, ar1);
        st4t(Bsm + lrow * PAD + lc4, br0);
        st4t(Bsm + (lrow + 64) * PAD + lc4, br1);
        __syncthreads();
        if (kt + 16 < DIM) {
            ar0 = *(const float4*)(Ap + kt + 16);
            ar1 = *(const float4*)(Ap + (size_t)64 * DIM + kt + 16);
            br0 = *(const float4*)(Wp + kt + 16);
            br1 = *(const float4*)(Wp + (size_t)64 * DIM + kt + 16);
        }
#pragma unroll
        for (int k8 = 0; k8 < 2; k8++) {
            uint32_t a[2][4], b[8][2];
#pragma unroll
            for (int t = 0; t < 2; t++) {
                const int r = wm * 32 + t * 16 + g;
                const int cb = k8 * 8 + tg;
                a[t][0] = Asm[r * PAD + cb];
                a[t][1] = Asm[(r + 8) * PAD + cb];
                a[t][2] = Asm[r * PAD + cb + 4];
                a[t][3] = Asm[(r + 8) * PAD + cb + 4];
            }
#pragma unroll
            for (int nt = 0; nt < 8; nt++) {
                const int nr = wn * 64 + nt * 8 + g;
                const int kc = k8 * 8 + tg;
                b[nt][0] = Bsm[nr * PAD + kc];
                b[nt][1] = Bsm[nr * PAD + kc + 4];
            }
#pragma unroll
            for (int t = 0; t < 2; t++)
#pragma unroll
                for (int nt = 0; nt < 8; nt++)
                    mma_tf32(c[t][nt], a[t], b[nt]);
        }
    }

    // epilogue: c0,c1 -> (row, col..col+1); c2,c3 -> (row+8, ..)
#pragma unroll
    for (int t = 0; t < 2; t++) {
        const int row0 = bm * 128 + wm * 32 + t * 16 + g;
#pragma unroll
        for (int nt = 0; nt < 8; nt++) {
            const int col = bn * 128 + wn * 64 + nt * 8 + 2 * tg;
            const float b0 = bias[col], b1 = bias[col + 1];
            float2 v0 = make_float2(c[t][nt].x + b0, c[t][nt].y + b1);
            float2 v1 = make_float2(c[t][nt].z + b0, c[t][nt].w + b1);
            const int h = col >> 6, d = col & 63;
            if (MODE == 0) {
                const int bb0 = row0 >> 9, s0 = row0 & 511;
                *(float2*)(out + ((size_t)(bb0 * NH + h) * S_LEN + s0) * HD + d) = v0;
                const int r1 = row0 + 8;
                const int bb1 = r1 >> 9, s1 = r1 & 511;
                *(float2*)(out + ((size_t)(bb1 * NH + h) * S_LEN + s1) * HD + d) = v1;
            } else {
                *(float2*)(out + ((size_t)h * POSJ + row0) * HD + d) = v0;
                *(float2*)(out + ((size_t)h * POSJ + row0 + 8) * HD + d) = v1;
            }
        }
    }
}

// ---------------------------------------------------------------------------
// tf32 banded rel GEMMs. Per bh: A [512,64] (q or k), B [1024,64] (pos emb).
// Block tile 128x128 over (m, j), K=64. Gathered epilogue into band layout.
// MODE 0 (c2p): k = m - n + 512 -> g_c2p[bh][m][k]
// MODE 1 (p2c): q = m + n - 512 -> g_p2c[bh][m][q]
// ---------------------------------------------------------------------------
template <int MODE>
__global__ void __launch_bounds__(256) rel_tf32()
{
    __shared__ uint32_t Asm[128 * PAD];
    __shared__ uint32_t Bsm[128 * PAD];

    const int tid  = threadIdx.x;
    const int warp = tid >> 5, lane = tid & 31;
    const int wm = warp >> 1, wn = warp & 1;
    const int g  = lane >> 2, tg = lane & 3;
    const int bn = blockIdx.x, bm = blockIdx.y, bh = blockIdx.z;
    const int h = bh & (NH - 1);

    const float* A  = (MODE == 0 ? g_q : g_k) + (size_t)bh * S_LEN * HD;
    const float* Bm = (MODE == 0 ? g_posk : g_posq) + (size_t)h * POSJ * HD;
    float* out      = (MODE == 0 ? g_c2p : g_p2c) + (size_t)bh * S_LEN * S_LEN;

    const int lrow = tid >> 2;
    const int lc4  = (tid & 3) << 2;

    const float* Ap = A  + (size_t)(bm * 128 + lrow) * HD + lc4;
    const float* Bp = Bm + (size_t)(bn * 128 + lrow) * HD + lc4;

    float4 ar0 = *(const float4*)(Ap);
    float4 ar1 = *(const float4*)(Ap + 64 * HD);
    float4 br0 = *(const float4*)(Bp);
    float4 br1 = *(const float4*)(Bp + 64 * HD);

    float4 c[2][8];
#pragma unroll
    for (int t = 0; t < 2; t++)
#pragma unroll
        for (int n = 0; n < 8; n++) c[t][n] = make_float4(0.f, 0.f, 0.f, 0.f);

#pragma unroll
    for (int kt = 0; kt < HD; kt += 16) {
        __syncthreads();
        st4t(Asm + lrow * PAD + lc4, ar0);
        st4t(Asm + (lrow + 64) * PAD + lc4, ar1);
        st4t(Bsm + lrow * PAD + lc4, br0);
        st4t(Bsm + (lrow + 64) * PAD + lc4, br1);
        __syncthreads();
        if (kt + 16 < HD) {
            ar0 = *(const float4*)(Ap + kt + 16);
            ar1 = *(const float4*)(Ap + 64 * HD + kt + 16);
            br0 = *(const float4*)(Bp + kt + 16);
            br1 = *(const float4*)(Bp + 64 * HD + kt + 16);
        }
#pragma unroll
        for (int k8 = 0; k8 < 2; k8++) {
            uint32_t a[2][4], b[8][2];
#pragma unroll
            for (int t = 0; t < 2; t++) {
                const int r = wm * 32 + t * 16 + g;
                const int cb = k8 * 8 + tg;
                a[t][0] = Asm[r * PAD + cb];
                a[t][1] = Asm[(r + 8) * PAD + cb];
                a[t][2] = Asm[r * PAD + cb + 4];
                a[t][3] = Asm[(r + 8) * PAD + cb + 4];
            }
#pragma unroll
            for (int nt = 0; nt < 8; nt++) {
                const int nr = wn * 64 + nt * 8 + g;
                const int kc = k8 * 8 + tg;
                b[nt][0] = Bsm[nr * PAD + kc];
                b[nt][1] = Bsm[nr * PAD + kc + 4];
            }
#pragma unroll
            for (int t = 0; t < 2; t++)
#pragma unroll
                for (int nt = 0; nt < 8; nt++)
                    mma_tf32(c[t][nt], a[t], b[nt]);
        }
    }

#pragma unroll
    for (int t = 0; t < 2; t++) {
        const int row0 = bm * 128 + wm * 32 + t * 16 + g;
#pragma unroll
        for (int nt = 0; nt < 8; nt++) {
            const int col = bn * 128 + wn * 64 + nt * 8 + 2 * tg;
            const float v[2][2] = {{c[t][nt].x, c[t][nt].y}, {c[t][nt].z, c[t][nt].w}};
#pragma unroll
            for (int rr = 0; rr < 2; rr++) {
                const int m = row0 + rr * 8;
#pragma unroll
                for (int cc = 0; cc < 2; cc++) {
                    const int n = col + cc;
                    if (MODE == 0) {
                        const int k = m - n + 512;
                        if ((unsigned)k < S_LEN) out[(size_t)m * S_LEN + k] = v[rr][cc];
                    } else {
                        const int q = m + n - 512;
                        if ((unsigned)q < S_LEN) out[(size_t)m * S_LEN + q] = v[rr][cc];
                    }
                }
            }
        }
    }
}

// ---------------------------------------------------------------------------
// Fused attention (unchanged from passing round-2 kernel).
// ---------------------------------------------------------------------------
#define ATTN_SMEM_BYTES ((64 * 64 + 64 * 64 + 64 * 68) * 4)

__global__ void __launch_bounds__(256) attn_kernel(const float* __restrict__ mask,
                                                   float* __restrict__ out)
{
    extern __shared__ float sm[];
    float* QsT  = sm;
    float* BufK = sm + 64 * 64;
    float* BufP = sm + 2 * 64 * 64;

    const int tid = threadIdx.x;
    const int bh = blockIdx.y;
    const int b = bh >> 4, h = bh & 15;
    const int q0 = blockIdx.x << 6;
    const int ty = tid >> 4, tx = tid & 15;

#pragma unroll
    for (int r = 0; r < 4; r++) {
        const int idx = tid + r * 256;
        const int row = idx >> 4, c = (idx & 15) << 2;
        float4 v = *(const float4*)(g_q + ((size_t)bh * S_LEN + q0 + row) * HD + c);
        QsT[(c + 0) * 64 + row] = v.x; QsT[(c + 1) * 64 + row] = v.y;
        QsT[(c + 2) * 64 + row] = v.z; QsT[(c + 3) * 64 + row] = v.w;
    }

    float m_i[4], l_i[4], acc[4][4];
#pragma unroll
    for (int i = 0; i < 4; i++) {
        m_i[i] = -1e30f; l_i[i] = 0.f;
#pragma unroll
        for (int j = 0; j < 4; j++) acc[i][j] = 0.f;
    }

    for (int kt = 0; kt < 8; kt++) {
        const int k0 = kt << 6;
        __syncthreads();
#pragma unroll
        for (int r = 0; r < 4; r++) {
            const int idx = tid + r * 256;
            const int row = idx >> 4, c = (idx & 15) << 2;
            float4 kv = *(const float4*)(g_k + ((size_t)bh * S_LEN + k0 + row) * HD + c);
            BufK[(c + 0) * 64 + row] = kv.x; BufK[(c + 1) * 64 + row] = kv.y;
            BufK[(c + 2) * 64 + row] = kv.z; BufK[(c + 3) * 64 + row] = kv.w;
            float4 pv = *(const float4*)(g_p2c + ((size_t)bh * S_LEN + k0 + row) * S_LEN + q0 + c);
            *(float4*)&BufP[row * 68 + c] = pv;
        }
        __syncthreads();

        float s[4][4];
#pragma unroll
        for (int j = 0; j < 4; j++) {
            const float4 pv = *(const float4*)&BufP[((tx << 2) + j) * 68 + (ty << 2)];
            s[0][j] = pv.x; s[1][j] = pv.y; s[2][j] = pv.z; s[3][j] = pv.w;
        }
#pragma unroll
        for (int i = 0; i < 4; i++) {
            const float4 c4 = *(const float4*)(g_c2p +
                ((size_t)bh * S_LEN + q0 + (ty << 2) + i) * S_LEN + k0 + (tx << 2));
            s[i][0] += c4.x; s[i][1] += c4.y; s[i][2] += c4.z; s[i][3] += c4.w;
        }
#pragma unroll
        for (int d = 0; d < 64; d++) {
            const float4 a4 = *(const float4*)&QsT[d * 64 + (ty << 2)];
            const float4 b4 = *(const float4*)&BufK[d * 64 + (tx << 2)];
            const float a[4] = {a4.x, a4.y, a4.z, a4.w};
            const float bb[4] = {b4.x, b4.y, b4.z, b4.w};
#pragma unroll
            for (int i = 0; i < 4; i++)
#pragma unroll
                for (int j = 0; j < 4; j++)
                    s[i][j] = fmaf(a[i], bb[j], s[i][j]);
        }
        const float4 mv = *(const float4*)(mask + b * S_LEN + k0 + (tx << 2));
        const float mk[4] = {mv.x, mv.y, mv.z, mv.w};
#pragma unroll
        for (int i = 0; i < 4; i++)
#pragma unroll
            for (int j = 0; j < 4; j++)
                s[i][j] = s[i][j] * SCORE_SCALE + mk[j];

        __syncthreads();

#pragma unroll
        for (int i = 0; i < 4; i++) {
            float rm = fmaxf(fmaxf(s[i][0], s[i][1]), fmaxf(s[i][2], s[i][3]));
#pragma unroll
            for (int o = 8; o >= 1; o >>= 1)
                rm = fmaxf(rm, __shfl_xor_sync(0xffffffffu, rm, o));
            const float mn = fmaxf(m_i[i], rm);
            const float sc = __expf(m_i[i] - mn);
            float rs = 0.f;
#pragma unroll
            for (int j = 0; j < 4; j++) {
                const float p = __expf(s[i][j] - mn);
                rs += p;
                BufP[((tx << 2) + j) * 68 + (ty << 2) + i] = p;
            }
#pragma unroll
            for (int o = 8; o >= 1; o >>= 1)
                rs += __shfl_xor_sync(0xffffffffu, rs, o);
            l_i[i] = l_i[i] * sc + rs;
            m_i[i] = mn;
#pragma unroll
            for (int j = 0; j < 4; j++) acc[i][j] *= sc;
        }
#pragma unroll
        for (int r = 0; r < 4; r++) {
            const int idx = tid + r * 256;
            const int row = idx >> 4, c = (idx & 15) << 2;
            float4 vv = *(const float4*)(g_v + ((size_t)bh * S_LEN + k0 + row) * HD + c);
            *(float4*)&BufK[row * 64 + c] = vv;
        }
        __syncthreads();

#pragma unroll
        for (int k = 0; k < 64; k++) {
            const float4 p4 = *(const float4*)&BufP[k * 68 + (ty << 2)];
            const float4 v4 = *(const float4*)&BufK[k * 64 + (tx << 2)];
            const float p[4] = {p4.x, p4.y, p4.z, p4.w};
            const float vv[4] = {v4.x, v4.y, v4.z, v4.w};
#pragma unroll
            for (int i = 0; i < 4; i++)
#pragma unroll
                for (int j = 0; j < 4; j++)
                    acc[i][j] = fmaf(p[i], vv[j], acc[i][j]);
        }
    }

#pragma unroll
    for (int i = 0; i < 4; i++) {
        const float inv = 1.0f / l_i[i];
        const int q = q0 + (ty << 2) + i;
        float4 o;
        o.x = acc[i][0] * inv; o.y = acc[i][1] * inv;
        o.z = acc[i][2] * inv; o.w = acc[i][3] * inv;
        *(float4*)(out + ((size_t)b * S_LEN + q) * DIM + h * HD + (tx << 2)) = o;
    }
}

// ---------------------------------------------------------------------------
extern "C" void kernel_launch(void* const* d_in, const int* in_sizes, int n_in,
                              void* d_out, int out_size)
{
    const float* x    = (const float*)d_in[0];
    const float* rel  = (const float*)d_in[1];
    const float* mask = (const float*)d_in[2];
    const float* Wq   = (const float*)d_in[3];
    const float* bq   = (const float*)d_in[4];
    const float* Wk   = (const float*)d_in[5];
    const float* bk   = (const float*)d_in[6];
    const float* Wv   = (const float*)d_in[7];
    const float* bv   = (const float*)d_in[8];
    float* out = (float*)d_out;

    const dim3 blk(256);

    // tf32 tensor-core projections
    proj_tf32<0, 0><<<dim3(8, 32), blk>>>(x, Wq, bq);
    proj_tf32<0, 1><<<dim3(8, 32), blk>>>(x, Wk, bk);
    proj_tf32<0, 2><<<dim3(8, 32), blk>>>(x, Wv, bv);
    proj_tf32<1, 3><<<dim3(8, 8), blk>>>(rel, Wq, bq);
    proj_tf32<1, 4><<<dim3(8, 8), blk>>>(rel, Wk, bk);

    // tf32 banded relative-position GEMMs
    rel_tf32<0><<<dim3(8, 4, BH), blk>>>();
    rel_tf32<1><<<dim3(8, 4, BH), blk>>>();

    // fused attention
    cudaFuncSetAttribute(attn_kernel, cudaFuncAttributeMaxDynamicSharedMemorySize,
                         ATTN_SMEM_BYTES);
    attn_kernel<<<dim3(8, BH), blk, ATTN_SMEM_BYTES>>>(mask, out);
}

// round 6
// speedup vs baseline: 3.0605x; 1.4801x over previous
#include <cuda_runtime.h>
#include <cuda_fp16.h>
#include <math.h>
#include <stdint.h>

#define S_LEN 512
#define HD    64
#define NH    16
#define NB    8
#define BH    128          // NB*NH
#define DIM   1024
#define POSJ  1024
#define SCORE_SCALE 0.07216878364870322f   // 1/sqrt(64*3)
#define PAD   20           // proj smem row pitch (u32)

// ---------------- scratch (static device globals; no runtime allocation) ----
__device__ __half g_qh[BH * S_LEN * HD];           // [b,h,s,d]
__device__ __half g_kh[BH * S_LEN * HD];
__device__ __half g_vh[BH * S_LEN * HD];
__device__ __half g_posqh[NH * POSJ * HD];         // [h,j,d]
__device__ __half g_poskh[NH * POSJ * HD];

// ---------------------------------------------------------------------------
// tf32 helpers (projection GEMMs)
// ---------------------------------------------------------------------------
__device__ __forceinline__ uint32_t f2t(float x) {
    uint32_t u; asm("cvt.rna.tf32.f32 %0, %1;" : "=r"(u) : "f"(x)); return u;
}
__device__ __forceinline__ void st4t(uint32_t* p, float4 v) {
    uint4 u; u.x = f2t(v.x); u.y = f2t(v.y); u.z = f2t(v.z); u.w = f2t(v.w);
    *(uint4*)p = u;
}
__device__ __forceinline__ void mma_tf32(float4& c, const uint32_t* a, const uint32_t* b) {
    asm volatile(
        "mma.sync.aligned.m16n8k8.row.col.f32.tf32.tf32.f32 "
        "{%0,%1,%2,%3}, {%4,%5,%6,%7}, {%8,%9}, {%0,%1,%2,%3};\n"
        : "+f"(c.x), "+f"(c.y), "+f"(c.z), "+f"(c.w)
        : "r"(a[0]), "r"(a[1]), "r"(a[2]), "r"(a[3]), "r"(b[0]), "r"(b[1]));
}
// fp16 mma, f32 accumulate (attention)
__device__ __forceinline__ void mma_f16(float4& c, const uint32_t* a, const uint32_t* b) {
    asm volatile(
        "mma.sync.aligned.m16n8k16.row.col.f32.f16.f16.f32 "
        "{%0,%1,%2,%3}, {%4,%5,%6,%7}, {%8,%9}, {%0,%1,%2,%3};\n"
        : "+f"(c.x), "+f"(c.y), "+f"(c.z), "+f"(c.w)
        : "r"(a[0]), "r"(a[1]), "r"(a[2]), "r"(a[3]), "r"(b[0]), "r"(b[1]));
}

// ---------------------------------------------------------------------------
// tf32 projection GEMM: C[m,n] = sum_k A[m,k] * W[n,k] + bias[n]  -> __half
// Block 128x128, BK=16, 256 threads = 8 warps (4m x 2n), warp tile 32x64.
// MODE 0: store to [b,h,s,d]; MODE 1: store to [h,j,d].
// ---------------------------------------------------------------------------
template <int MODE, int DST>
__global__ void __launch_bounds__(256) proj_tf32(const float* __restrict__ A,
                                                 const float* __restrict__ W,
                                                 const float* __restrict__ bias)
{
    __half* out = (DST == 0) ? g_qh : (DST == 1) ? g_kh : (DST == 2) ? g_vh
                : (DST == 3) ? g_posqh : g_poskh;

    __shared__ uint32_t Asm[128 * PAD];
    __shared__ uint32_t Bsm[128 * PAD];

    const int tid  = threadIdx.x;
    const int warp = tid >> 5, lane = tid & 31;
    const int wm = warp >> 1, wn = warp & 1;
    const int g  = lane >> 2, tg = lane & 3;
    const int bm = blockIdx.y, bn = blockIdx.x;

    const int lrow = tid >> 2;
    const int lc4  = (tid & 3) << 2;

    const float* Ap = A + (size_t)(bm * 128 + lrow) * DIM + lc4;
    const float* Wp = W + (size_t)(bn * 128 + lrow) * DIM + lc4;

    float4 ar0 = *(const float4*)(Ap);
    float4 ar1 = *(const float4*)(Ap + (size_t)64 * DIM);
    float4 br0 = *(const float4*)(Wp);
    float4 br1 = *(const float4*)(Wp + (size_t)64 * DIM);

    float4 c[2][8];
#pragma unroll
    for (int t = 0; t < 2; t++)
#pragma unroll
        for (int n = 0; n < 8; n++) c[t][n] = make_float4(0.f, 0.f, 0.f, 0.f);

    for (int kt = 0; kt < DIM; kt += 16) {
        __syncthreads();
        st4t(Asm + lrow * PAD + lc4, ar0);
        st4t(Asm + (lrow + 64) * PAD + lc4, ar1);
        st4t(Bsm + lrow * PAD + lc4, br0);
        st4t(Bsm + (lrow + 64) * PAD + lc4, br1);
        __syncthreads();
        if (kt + 16 < DIM) {
            ar0 = *(const float4*)(Ap + kt + 16);
            ar1 = *(const float4*)(Ap + (size_t)64 * DIM + kt + 16);
            br0 = *(const float4*)(Wp + kt + 16);
            br1 = *(const float4*)(Wp + (size_t)64 * DIM + kt + 16);
        }
#pragma unroll
        for (int k8 = 0; k8 < 2; k8++) {
            uint32_t a[2][4], b[8][2];
#pragma unroll
            for (int t = 0; t < 2; t++) {
                const int r = wm * 32 + t * 16 + g;
                const int cb = k8 * 8 + tg;
                a[t][0] = Asm[r * PAD + cb];
                a[t][1] = Asm[(r + 8) * PAD + cb];
                a[t][2] = Asm[r * PAD + cb + 4];
                a[t][3] = Asm[(r + 8) * PAD + cb + 4];
            }
#pragma unroll
            for (int nt = 0; nt < 8; nt++) {
                const int nr = wn * 64 + nt * 8 + g;
                const int kc = k8 * 8 + tg;
                b[nt][0] = Bsm[nr * PAD + kc];
                b[nt][1] = Bsm[nr * PAD + kc + 4];
            }
#pragma unroll
            for (int t = 0; t < 2; t++)
#pragma unroll
                for (int nt = 0; nt < 8; nt++)
                    mma_tf32(c[t][nt], a[t], b[nt]);
        }
    }

#pragma unroll
    for (int t = 0; t < 2; t++) {
        const int row0 = bm * 128 + wm * 32 + t * 16 + g;
#pragma unroll
        for (int nt = 0; nt < 8; nt++) {
            const int col = bn * 128 + wn * 64 + nt * 8 + 2 * tg;
            const float b0 = bias[col], b1 = bias[col + 1];
            __half2 h0 = __floats2half2_rn(c[t][nt].x + b0, c[t][nt].y + b1);
            __half2 h1 = __floats2half2_rn(c[t][nt].z + b0, c[t][nt].w + b1);
            const int h = col >> 6, d = col & 63;
            if (MODE == 0) {
                const int bb0 = row0 >> 9, s0 = row0 & 511;
                *(__half2*)(out + ((size_t)(bb0 * NH + h) * S_LEN + s0) * HD + d) = h0;
                const int r1 = row0 + 8;
                const int bb1 = r1 >> 9, s1 = r1 & 511;
                *(__half2*)(out + ((size_t)(bb1 * NH + h) * S_LEN + s1) * HD + d) = h1;
            } else {
                *(__half2*)(out + ((size_t)h * POSJ + row0) * HD + d) = h0;
                *(__half2*)(out + ((size_t)h * POSJ + row0 + 8) * HD + d) = h1;
            }
        }
    }
}

// ---------------------------------------------------------------------------
// Fused fp16 tensor-core attention with in-tile c2p/p2c band GEMMs.
// CTA = 128 threads (4 warps), q-tile 64, k-tiles of 64.
// c2p[q,k] = Q[q]·posK[q-k+512]
// p2c[q,k] = K[k]·posQ[q-k+512]      (same relative index — verified vs ref)
// Band rows r=0..127 map to j = q0-k0+449+r for BOTH bands.
// c2p gather: Prod[q][q-k+63]; p2c gather: Prod[k][q-k+63].
// ---------------------------------------------------------------------------
#define SM_QH    0
#define SM_KSH   9216
#define SM_VTH   18432
#define SM_BAND  27648
#define SM_PROD  46080
#define SM_PS    79872
#define SM_MASK  89088
#define ATTN2_SMEM (89088 + 2048)

__global__ void __launch_bounds__(128) attn2_kernel(const float* __restrict__ mask,
                                                    float* __restrict__ out)
{
    extern __shared__ char smraw[];
    __half* Qh   = (__half*)(smraw + SM_QH);     // [64][72]
    __half* Ksh  = (__half*)(smraw + SM_KSH);    // [64][72]
    __half* Vth  = (__half*)(smraw + SM_VTH);    // [64][72] (V transposed: [d][k])
    __half* Bandh= (__half*)(smraw + SM_BAND);   // [128][72]
    float*  Prod = (float*)(smraw + SM_PROD);    // [64][132]
    __half* Ps   = (__half*)(smraw + SM_PS);     // [64][72]
    float*  Mf   = (float*)(smraw + SM_MASK);    // [512]

    const int tid = threadIdx.x;
    const int w = tid >> 5, lane = tid & 31;
    const int g = lane >> 2, tg = lane & 3;
    const int bh = blockIdx.y;
    const int b = bh >> 4, h = bh & 15;
    const int q0 = blockIdx.x << 6;

    // ---- prologue: load Q tile + mask row -----------------------------------
    {
        const int row = tid >> 1, seg = tid & 1;
        const uint4* src = (const uint4*)(g_qh + ((size_t)bh * S_LEN + q0 + row) * HD + seg * 32);
        uint4* dst = (uint4*)(Qh + row * 72 + seg * 32);
#pragma unroll
        for (int i = 0; i < 4; i++) dst[i] = src[i];
        *(float4*)(Mf + tid * 4) = *(const float4*)(mask + b * S_LEN + tid * 4);
    }

    const int qq = 16 * w + g;            // this thread's base S row (tile-local)

    float4 sfr[8], acc[8];
    float m0 = -1e30f, m1 = -1e30f, l0 = 0.f, l1 = 0.f;
#pragma unroll
    for (int f = 0; f < 8; f++) acc[f] = make_float4(0.f, 0.f, 0.f, 0.f);

    for (int kt = 0; kt < 8; kt++) {
        const int k0 = kt << 6;
        __syncthreads();

        // ---- loads: K tile, V transposed, posK band -------------------------
        {
            const int row = tid >> 1, seg = tid & 1;
            const uint4* ks = (const uint4*)(g_kh + ((size_t)bh * S_LEN + k0 + row) * HD + seg * 32);
            uint4* kd = (uint4*)(Ksh + row * 72 + seg * 32);
#pragma unroll
            for (int i = 0; i < 4; i++) kd[i] = ks[i];

            const __half2* vs = (const __half2*)(g_vh + ((size_t)bh * S_LEN + k0 + row) * HD + seg * 32);
#pragma unroll
            for (int i = 0; i < 16; i++) {
                __half2 v = vs[i];
                const int d = seg * 32 + 2 * i;
                Vth[d * 72 + row] = __low2half(v);
                Vth[(d + 1) * 72 + row] = __high2half(v);
            }
            // posK band: row r = tid, j = q0 - k0 + 449 + r, clamped
            int j = q0 - k0 + 449 + tid;
            j = j < 0 ? 0 : (j > 1023 ? 1023 : j);
            const uint4* bs = (const uint4*)(g_poskh + ((size_t)h * POSJ + j) * HD);
            uint4* bd = (uint4*)(Bandh + tid * 72);
#pragma unroll
            for (int i = 0; i < 8; i++) bd[i] = bs[i];
        }
        __syncthreads();

        // ---- S = Q K^T ------------------------------------------------------
#pragma unroll
        for (int f = 0; f < 8; f++) sfr[f] = make_float4(0.f, 0.f, 0.f, 0.f);
#pragma unroll
        for (int c = 0; c < 4; c++) {
            uint32_t a[4];
            const __half* qr = Qh + qq * 72 + 16 * c + 2 * tg;
            a[0] = *(const uint32_t*)qr;
            a[1] = *(const uint32_t*)(qr + 8 * 72);
            a[2] = *(const uint32_t*)(qr + 8);
            a[3] = *(const uint32_t*)(qr + 8 * 72 + 8);
#pragma unroll
            for (int f = 0; f < 8; f++) {
                uint32_t bb[2];
                const __half* kb = Ksh + (8 * f + g) * 72 + 16 * c + 2 * tg;
                bb[0] = *(const uint32_t*)kb;
                bb[1] = *(const uint32_t*)(kb + 8);
                mma_f16(sfr[f], a, bb);
            }
        }

        // ---- C2P = Q @ posK_band^T -> Prod [64][128] ------------------------
#pragma unroll
        for (int pass = 0; pass < 2; pass++) {
            float4 t[8];
#pragma unroll
            for (int f = 0; f < 8; f++) t[f] = make_float4(0.f, 0.f, 0.f, 0.f);
#pragma unroll
            for (int c = 0; c < 4; c++) {
                uint32_t a[4];
                const __half* qr = Qh + qq * 72 + 16 * c + 2 * tg;
                a[0] = *(const uint32_t*)qr;
                a[1] = *(const uint32_t*)(qr + 8 * 72);
                a[2] = *(const uint32_t*)(qr + 8);
                a[3] = *(const uint32_t*)(qr + 8 * 72 + 8);
#pragma unroll
                for (int f = 0; f < 8; f++) {
                    uint32_t bb[2];
                    const __half* pb = Bandh + (64 * pass + 8 * f + g) * 72 + 16 * c + 2 * tg;
                    bb[0] = *(const uint32_t*)pb;
                    bb[1] = *(const uint32_t*)(pb + 8);
                    mma_f16(t[f], a, bb);
                }
            }
#pragma unroll
            for (int f = 0; f < 8; f++) {
                float* p0 = Prod + qq * 132 + 64 * pass + 8 * f + 2 * tg;
                p0[0] = t[f].x; p0[1] = t[f].y;
                p0[8 * 132] = t[f].z; p0[8 * 132 + 1] = t[f].w;
            }
        }
        __syncthreads();

        // ---- gather c2p into S (Prod[q][q-k+63]); load posQ band ------------
#pragma unroll
        for (int f = 0; f < 8; f++) {
            const int kk = 8 * f + 2 * tg;
            sfr[f].x += Prod[qq * 132 + qq - kk + 63];
            sfr[f].y += Prod[qq * 132 + qq - kk + 62];
            sfr[f].z += Prod[(qq + 8) * 132 + qq - kk + 71];
            sfr[f].w += Prod[(qq + 8) * 132 + qq - kk + 70];
        }
        {
            // p2c band uses the SAME index mapping: j = q0 - k0 + 449 + r
            int j = q0 - k0 + 449 + tid;
            j = j < 0 ? 0 : (j > 1023 ? 1023 : j);
            const uint4* bs = (const uint4*)(g_posqh + ((size_t)h * POSJ + j) * HD);
            uint4* bd = (uint4*)(Bandh + tid * 72);
#pragma unroll
            for (int i = 0; i < 8; i++) bd[i] = bs[i];
        }
        __syncthreads();

        // ---- P2C = K @ posQ_band^T -> Prod ----------------------------------
#pragma unroll
        for (int pass = 0; pass < 2; pass++) {
            float4 t[8];
#pragma unroll
            for (int f = 0; f < 8; f++) t[f] = make_float4(0.f, 0.f, 0.f, 0.f);
#pragma unroll
            for (int c = 0; c < 4; c++) {
                uint32_t a[4];
                const __half* kr = Ksh + qq * 72 + 16 * c + 2 * tg;
                a[0] = *(const uint32_t*)kr;
                a[1] = *(const uint32_t*)(kr + 8 * 72);
                a[2] = *(const uint32_t*)(kr + 8);
                a[3] = *(const uint32_t*)(kr + 8 * 72 + 8);
#pragma unroll
                for (int f = 0; f < 8; f++) {
                    uint32_t bb[2];
                    const __half* pb = Bandh + (64 * pass + 8 * f + g) * 72 + 16 * c + 2 * tg;
                    bb[0] = *(const uint32_t*)pb;
                    bb[1] = *(const uint32_t*)(pb + 8);
                    mma_f16(t[f], a, bb);
                }
            }
#pragma unroll
            for (int f = 0; f < 8; f++) {
                float* p0 = Prod + qq * 132 + 64 * pass + 8 * f + 2 * tg;
                p0[0] = t[f].x; p0[1] = t[f].y;
                p0[8 * 132] = t[f].z; p0[8 * 132 + 1] = t[f].w;
            }
        }
        __syncthreads();

        // ---- gather p2c (Prod[k][q-k+63]), scale + mask ---------------------
#pragma unroll
        for (int f = 0; f < 8; f++) {
            const int kk = 8 * f + 2 * tg;
            sfr[f].x += Prod[kk * 132 + qq - kk + 63];
            sfr[f].y += Prod[(kk + 1) * 132 + qq - kk + 62];
            sfr[f].z += Prod[kk * 132 + qq - kk + 71];
            sfr[f].w += Prod[(kk + 1) * 132 + qq - kk + 70];
            const float mk0 = Mf[k0 + kk], mk1 = Mf[k0 + kk + 1];
            sfr[f].x = sfr[f].x * SCORE_SCALE + mk0;
            sfr[f].y = sfr[f].y * SCORE_SCALE + mk1;
            sfr[f].z = sfr[f].z * SCORE_SCALE + mk0;
            sfr[f].w = sfr[f].w * SCORE_SCALE + mk1;
        }

        // ---- online softmax -------------------------------------------------
        float r0 = -1e30f, r1 = -1e30f;
#pragma unroll
        for (int f = 0; f < 8; f++) {
            r0 = fmaxf(r0, fmaxf(sfr[f].x, sfr[f].y));
            r1 = fmaxf(r1, fmaxf(sfr[f].z, sfr[f].w));
        }
        r0 = fmaxf(r0, __shfl_xor_sync(0xffffffffu, r0, 1));
        r0 = fmaxf(r0, __shfl_xor_sync(0xffffffffu, r0, 2));
        r1 = fmaxf(r1, __shfl_xor_sync(0xffffffffu, r1, 1));
        r1 = fmaxf(r1, __shfl_xor_sync(0xffffffffu, r1, 2));
        const float nm0 = fmaxf(m0, r0), nm1 = fmaxf(m1, r1);
        const float sc0 = __expf(m0 - nm0), sc1 = __expf(m1 - nm1);
        float rs0 = 0.f, rs1 = 0.f;
#pragma unroll
        for (int f = 0; f < 8; f++) {
            const float px = __expf(sfr[f].x - nm0);
            const float py = __expf(sfr[f].y - nm0);
            const float pz = __expf(sfr[f].z - nm1);
            const float pw = __expf(sfr[f].w - nm1);
            rs0 += px + py; rs1 += pz + pw;
            *(__half2*)(Ps + qq * 72 + 8 * f + 2 * tg) = __floats2half2_rn(px, py);
            *(__half2*)(Ps + (qq + 8) * 72 + 8 * f + 2 * tg) = __floats2half2_rn(pz, pw);
            acc[f].x *= sc0; acc[f].y *= sc0;
            acc[f].z *= sc1; acc[f].w *= sc1;
        }
        rs0 += __shfl_xor_sync(0xffffffffu, rs0, 1);
        rs0 += __shfl_xor_sync(0xffffffffu, rs0, 2);
        rs1 += __shfl_xor_sync(0xffffffffu, rs1, 1);
        rs1 += __shfl_xor_sync(0xffffffffu, rs1, 2);
        l0 = l0 * sc0 + rs0;
        l1 = l1 * sc1 + rs1;
        m0 = nm0; m1 = nm1;

        __syncwarp();   // Ps rows are warp-local; warp-level visibility suffices

        // ---- PV: acc += P @ V ----------------------------------------------
#pragma unroll
        for (int c = 0; c < 4; c++) {
            uint32_t a[4];
            const __half* pr = Ps + qq * 72 + 16 * c + 2 * tg;
            a[0] = *(const uint32_t*)pr;
            a[1] = *(const uint32_t*)(pr + 8 * 72);
            a[2] = *(const uint32_t*)(pr + 8);
            a[3] = *(const uint32_t*)(pr + 8 * 72 + 8);
#pragma unroll
            for (int f = 0; f < 8; f++) {
                uint32_t bb[2];
                const __half* vb = Vth + (8 * f + g) * 72 + 16 * c + 2 * tg;
                bb[0] = *(const uint32_t*)vb;
                bb[1] = *(const uint32_t*)(vb + 8);
                mma_f16(acc[f], a, bb);
            }
        }
    }

    // ---- epilogue: normalize, write [b, s, h*64+d] as f32 -------------------
    const float inv0 = 1.0f / l0, inv1 = 1.0f / l1;
    float* orow0 = out + ((size_t)b * S_LEN + q0 + qq) * DIM + h * HD;
    float* orow1 = orow0 + 8 * DIM;
#pragma unroll
    for (int f = 0; f < 8; f++) {
        const int col = 8 * f + 2 * tg;
        *(float2*)(orow0 + col) = make_float2(acc[f].x * inv0, acc[f].y * inv0);
        *(float2*)(orow1 + col) = make_float2(acc[f].z * inv1, acc[f].w * inv1);
    }
}

// ---------------------------------------------------------------------------
extern "C" void kernel_launch(void* const* d_in, const int* in_sizes, int n_in,
                              void* d_out, int out_size)
{
    const float* x    = (const float*)d_in[0];
    const float* rel  = (const float*)d_in[1];
    const float* mask = (const float*)d_in[2];
    const float* Wq   = (const float*)d_in[3];
    const float* bq   = (const float*)d_in[4];
    const float* Wk   = (const float*)d_in[5];
    const float* bk   = (const float*)d_in[6];
    const float* Wv   = (const float*)d_in[7];
    const float* bv   = (const float*)d_in[8];
    float* out = (float*)d_out;

    const dim3 blk(256);

    // tf32 tensor-core projections (outputs stored as fp16)
    proj_tf32<0, 0><<<dim3(8, 32), blk>>>(x, Wq, bq);
    proj_tf32<0, 1><<<dim3(8, 32), blk>>>(x, Wk, bk);
    proj_tf32<0, 2><<<dim3(8, 32), blk>>>(x, Wv, bv);
    proj_tf32<1, 3><<<dim3(8, 8), blk>>>(rel, Wq, bq);
    proj_tf32<1, 4><<<dim3(8, 8), blk>>>(rel, Wk, bk);

    // fused fp16 attention with in-tile c2p/p2c
    cudaFuncSetAttribute(attn2_kernel, cudaFuncAttributeMaxDynamicSharedMemorySize,
                         ATTN2_SMEM);
    attn2_kernel<<<dim3(8, BH), dim3(128), ATTN2_SMEM>>>(mask, out);
}

// round 9
// speedup vs baseline: 3.7396x; 1.2219x over previous
#include <cuda_runtime.h>
#include <cuda_fp16.h>
#include <math.h>
#include <stdint.h>

#define S_LEN 512
#define HD    64
#define NH    16
#define NB    8
#define BH    128          // NB*NH
#define DIM   1024
#define POSJ  1024
#define SCORE_SCALE 0.07216878364870322f   // 1/sqrt(64*3)
#define PPITCH 40          // proj smem row pitch in halves (conflict-free)

// ---------------- scratch (static device globals; no runtime allocation) ----
__device__ __half g_qh[BH * S_LEN * HD];           // [b,h,s,d]
__device__ __half g_kh[BH * S_LEN * HD];
__device__ __half g_vh[BH * S_LEN * HD];
__device__ __half g_posqh[NH * POSJ * HD];         // [h,j,d]
__device__ __half g_poskh[NH * POSJ * HD];

// ---------------------------------------------------------------------------
// fp16 mma, f32 accumulate
// ---------------------------------------------------------------------------
__device__ __forceinline__ void mma_f16(float4& c, const uint32_t* a, const uint32_t* b) {
    asm volatile(
        "mma.sync.aligned.m16n8k16.row.col.f32.f16.f16.f32 "
        "{%0,%1,%2,%3}, {%4,%5,%6,%7}, {%8,%9}, {%0,%1,%2,%3};\n"
        : "+f"(c.x), "+f"(c.y), "+f"(c.z), "+f"(c.w)
        : "r"(a[0]), "r"(a[1]), "r"(a[2]), "r"(a[3]), "r"(b[0]), "r"(b[1]));
}
__device__ __forceinline__ uint32_t p2(float a, float b) {
    __half2 h = __floats2half2_rn(a, b);
    return *(uint32_t*)&h;
}

// ---------------------------------------------------------------------------
// fp16 projection GEMM: C[m,n] = sum_k A[m,k]*W[n,k] + bias[n]  -> __half out
// Block 128x128, BK=32, 256 threads = 8 warps (4m x 2n), warp tile 32x64.
// grid.z selects (W, bias, out):
//   MODE 0 (token, A=x): z=0 Q, z=1 K, z=2 V        -> [b,h,s,d]
//   MODE 1 (pos, A=rel): z=0 posQ(Wq), z=1 posK(Wk) -> [h,j,d]
// ---------------------------------------------------------------------------
template <int MODE>
__global__ void __launch_bounds__(256) proj_f16(const float* __restrict__ A,
                                                const float* __restrict__ W0,
                                                const float* __restrict__ W1,
                                                const float* __restrict__ W2,
                                                const float* __restrict__ bias0,
                                                const float* __restrict__ bias1,
                                                const float* __restrict__ bias2)
{
    const int z = blockIdx.z;
    const float* W    = (z == 0) ? W0 : (z == 1) ? W1 : W2;
    const float* bias = (z == 0) ? bias0 : (z == 1) ? bias1 : bias2;
    __half* out = (MODE == 0) ? ((z == 0) ? g_qh : (z == 1) ? g_kh : g_vh)
                              : ((z == 0) ? g_posqh : g_poskh);

    __shared__ __half As[128 * PPITCH];
    __shared__ __half Bs[128 * PPITCH];

    const int tid  = threadIdx.x;
    const int warp = tid >> 5, lane = tid & 31;
    const int wm = warp >> 1, wn = warp & 1;
    const int g  = lane >> 2, tg = lane & 3;
    const int bm = blockIdx.y, bn = blockIdx.x;

    const int lrow = tid >> 1;          // 0..127
    const int seg  = tid & 1;           // 0,1 (16-float segment)

    const float* Ap = A + (size_t)(bm * 128 + lrow) * DIM + seg * 16;
    const float* Wp = W + (size_t)(bn * 128 + lrow) * DIM + seg * 16;

    float4 pa[4], pb[4];
#pragma unroll
    for (int i = 0; i < 4; i++) {
        pa[i] = ((const float4*)Ap)[i];
        pb[i] = ((const float4*)Wp)[i];
    }

    float4 c[2][8];
#pragma unroll
    for (int t = 0; t < 2; t++)
#pragma unroll
        for (int n = 0; n < 8; n++) c[t][n] = make_float4(0.f, 0.f, 0.f, 0.f);

    for (int kt = 0; kt < DIM; kt += 32) {
        __syncthreads();
        {
            uint4 ua0, ua1, ub0, ub1;
            ua0.x = p2(pa[0].x, pa[0].y); ua0.y = p2(pa[0].z, pa[0].w);
            ua0.z = p2(pa[1].x, pa[1].y); ua0.w = p2(pa[1].z, pa[1].w);
            ua1.x = p2(pa[2].x, pa[2].y); ua1.y = p2(pa[2].z, pa[2].w);
            ua1.z = p2(pa[3].x, pa[3].y); ua1.w = p2(pa[3].z, pa[3].w);
            ub0.x = p2(pb[0].x, pb[0].y); ub0.y = p2(pb[0].z, pb[0].w);
            ub0.z = p2(pb[1].x, pb[1].y); ub0.w = p2(pb[1].z, pb[1].w);
            ub1.x = p2(pb[2].x, pb[2].y); ub1.y = p2(pb[2].z, pb[2].w);
            ub1.z = p2(pb[3].x, pb[3].y); ub1.w = p2(pb[3].z, pb[3].w);
            __half* ad = As + lrow * PPITCH + seg * 16;
            __half* bd = Bs + lrow * PPITCH + seg * 16;
            *(uint4*)ad = ua0; *(uint4*)(ad + 8) = ua1;
            *(uint4*)bd = ub0; *(uint4*)(bd + 8) = ub1;
        }
        __syncthreads();
        if (kt + 32 < DIM) {
#pragma unroll
            for (int i = 0; i < 4; i++) {
                pa[i] = ((const float4*)(Ap + kt + 32))[i];
                pb[i] = ((const float4*)(Wp + kt + 32))[i];
            }
        }
#pragma unroll
        for (int k16 = 0; k16 < 2; k16++) {
            const int kb = k16 * 16 + 2 * tg;
            uint32_t a[2][4], b[8][2];
#pragma unroll
            for (int t = 0; t < 2; t++) {
                const __half* ar = As + (wm * 32 + t * 16 + g) * PPITCH + kb;
                a[t][0] = *(const uint32_t*)ar;
                a[t][1] = *(const uint32_t*)(ar + 8 * PPITCH);
                a[t][2] = *(const uint32_t*)(ar + 8);
                a[t][3] = *(const uint32_t*)(ar + 8 * PPITCH + 8);
            }
#pragma unroll
            for (int f = 0; f < 8; f++) {
                const __half* br = Bs + (wn * 64 + f * 8 + g) * PPITCH + kb;
                b[f][0] = *(const uint32_t*)br;
                b[f][1] = *(const uint32_t*)(br + 8);
            }
#pragma unroll
            for (int t = 0; t < 2; t++)
#pragma unroll
                for (int f = 0; f < 8; f++)
                    mma_f16(c[t][f], a[t], b[f]);
        }
    }

    // epilogue: add bias, convert to half, store scattered per layout
#pragma unroll
    for (int t = 0; t < 2; t++) {
        const int row0 = bm * 128 + wm * 32 + t * 16 + g;
#pragma unroll
        for (int f = 0; f < 8; f++) {
            const int col = bn * 128 + wn * 64 + f * 8 + 2 * tg;
            const float b0 = bias[col], b1 = bias[col + 1];
            __half2 h0 = __floats2half2_rn(c[t][f].x + b0, c[t][f].y + b1);
            __half2 h1 = __floats2half2_rn(c[t][f].z + b0, c[t][f].w + b1);
            const int h = col >> 6, d = col & 63;
            if (MODE == 0) {
                const int bb0 = row0 >> 9, s0 = row0 & 511;
                *(__half2*)(out + ((size_t)(bb0 * NH + h) * S_LEN + s0) * HD + d) = h0;
                const int r1 = row0 + 8;
                const int bb1 = r1 >> 9, s1 = r1 & 511;
                *(__half2*)(out + ((size_t)(bb1 * NH + h) * S_LEN + s1) * HD + d) = h1;
            } else {
                *(__half2*)(out + ((size_t)h * POSJ + row0) * HD + d) = h0;
                *(__half2*)(out + ((size_t)h * POSJ + row0 + 8) * HD + d) = h1;
            }
        }
    }
}

// ---------------------------------------------------------------------------
// Fused fp16 tensor-core attention with in-tile c2p/p2c band GEMMs.
// CTA = 128 threads (4 warps), q-tile 64, k-tiles of 64.
// c2p[q,k] = Q[q]·posK[q-k+512];  p2c[q,k] = K[k]·posQ[q-k+512]
// Band rows r=0..127 map to j = q0-k0+449+r for BOTH bands.
// c2p gather: Prod[q][q-k+63]; p2c gather: Prod[k][q-k+63].
// ---------------------------------------------------------------------------
#define SM_QH    0
#define SM_KSH   9216
#define SM_VTH   18432
#define SM_BAND  27648
#define SM_PROD  46080
#define SM_PS    79872
#define SM_MASK  89088
#define ATTN2_SMEM (89088 + 2048)

__global__ void __launch_bounds__(128) attn2_kernel(const float* __restrict__ mask,
                                                    float* __restrict__ out)
{
    extern __shared__ char smraw[];
    __half* Qh   = (__half*)(smraw + SM_QH);     // [64][72]
    __half* Ksh  = (__half*)(smraw + SM_KSH);    // [64][72]
    __half* Vth  = (__half*)(smraw + SM_VTH);    // [64][72] (V transposed: [d][k])
    __half* Bandh= (__half*)(smraw + SM_BAND);   // [128][72]
    float*  Prod = (float*)(smraw + SM_PROD);    // [64][132]
    __half* Ps   = (__half*)(smraw + SM_PS);     // [64][72]
    float*  Mf   = (float*)(smraw + SM_MASK);    // [512]

    const int tid = threadIdx.x;
    const int w = tid >> 5, lane = tid & 31;
    const int g = lane >> 2, tg = lane & 3;
    const int bh = blockIdx.y;
    const int b = bh >> 4, h = bh & 15;
    const int q0 = blockIdx.x << 6;

    // ---- prologue: load Q tile + mask row -----------------------------------
    {
        const int row = tid >> 1, seg = tid & 1;
        const uint4* src = (const uint4*)(g_qh + ((size_t)bh * S_LEN + q0 + row) * HD + seg * 32);
        uint4* dst = (uint4*)(Qh + row * 72 + seg * 32);
#pragma unroll
        for (int i = 0; i < 4; i++) dst[i] = src[i];
        *(float4*)(Mf + tid * 4) = *(const float4*)(mask + b * S_LEN + tid * 4);
    }

    const int qq = 16 * w + g;            // this thread's base S row (tile-local)

    float4 sfr[8], acc[8];
    float m0 = -1e30f, m1 = -1e30f, l0 = 0.f, l1 = 0.f;
#pragma unroll
    for (int f = 0; f < 8; f++) acc[f] = make_float4(0.f, 0.f, 0.f, 0.f);

    for (int kt = 0; kt < 8; kt++) {
        const int k0 = kt << 6;
        __syncthreads();

        // ---- loads: K tile, V transposed, posK band -------------------------
        {
            const int row = tid >> 1, seg = tid & 1;
            const uint4* ks = (const uint4*)(g_kh + ((size_t)bh * S_LEN + k0 + row) * HD + seg * 32);
            uint4* kd = (uint4*)(Ksh + row * 72 + seg * 32);
#pragma unroll
            for (int i = 0; i < 4; i++) kd[i] = ks[i];

            const __half2* vs = (const __half2*)(g_vh + ((size_t)bh * S_LEN + k0 + row) * HD + seg * 32);
#pragma unroll
            for (int i = 0; i < 16; i++) {
                __half2 v = vs[i];
                const int d = seg * 32 + 2 * i;
                Vth[d * 72 + row] = __low2half(v);
                Vth[(d + 1) * 72 + row] = __high2half(v);
            }
            // posK band: row r = tid, j = q0 - k0 + 449 + r, clamped
            int j = q0 - k0 + 449 + tid;
            j = j < 0 ? 0 : (j > 1023 ? 1023 : j);
            const uint4* bs = (const uint4*)(g_poskh + ((size_t)h * POSJ + j) * HD);
            uint4* bd = (uint4*)(Bandh + tid * 72);
#pragma unroll
            for (int i = 0; i < 8; i++) bd[i] = bs[i];
        }
        __syncthreads();

        // ---- S = Q K^T ------------------------------------------------------
#pragma unroll
        for (int f = 0; f < 8; f++) sfr[f] = make_float4(0.f, 0.f, 0.f, 0.f);
#pragma unroll
        for (int c = 0; c < 4; c++) {
            uint32_t a[4];
            const __half* qr = Qh + qq * 72 + 16 * c + 2 * tg;
            a[0] = *(const uint32_t*)qr;
            a[1] = *(const uint32_t*)(qr + 8 * 72);
            a[2] = *(const uint32_t*)(qr + 8);
            a[3] = *(const uint32_t*)(qr + 8 * 72 + 8);
#pragma unroll
            for (int f = 0; f < 8; f++) {
                uint32_t bb[2];
                const __half* kb = Ksh + (8 * f + g) * 72 + 16 * c + 2 * tg;
                bb[0] = *(const uint32_t*)kb;
                bb[1] = *(const uint32_t*)(kb + 8);
                mma_f16(sfr[f], a, bb);
            }
        }

        // ---- C2P = Q @ posK_band^T -> Prod [64][128] ------------------------
#pragma unroll
        for (int pass = 0; pass < 2; pass++) {
            float4 t[8];
#pragma unroll
            for (int f = 0; f < 8; f++) t[f] = make_float4(0.f, 0.f, 0.f, 0.f);
#pragma unroll
            for (int c = 0; c < 4; c++) {
                uint32_t a[4];
                const __half* qr = Qh + qq * 72 + 16 * c + 2 * tg;
                a[0] = *(const uint32_t*)qr;
                a[1] = *(const uint32_t*)(qr + 8 * 72);
                a[2] = *(const uint32_t*)(qr + 8);
                a[3] = *(const uint32_t*)(qr + 8 * 72 + 8);
#pragma unroll
                for (int f = 0; f < 8; f++) {
                    uint32_t bb[2];
                    const __half* pb = Bandh + (64 * pass + 8 * f + g) * 72 + 16 * c + 2 * tg;
                    bb[0] = *(const uint32_t*)pb;
                    bb[1] = *(const uint32_t*)(pb + 8);
                    mma_f16(t[f], a, bb);
                }
            }
#pragma unroll
            for (int f = 0; f < 8; f++) {
                float* p0 = Prod + qq * 132 + 64 * pass + 8 * f + 2 * tg;
                p0[0] = t[f].x; p0[1] = t[f].y;
                p0[8 * 132] = t[f].z; p0[8 * 132 + 1] = t[f].w;
            }
        }
        __syncthreads();

        // ---- gather c2p into S (Prod[q][q-k+63]); load posQ band ------------
#pragma unroll
        for (int f = 0; f < 8; f++) {
            const int kk = 8 * f + 2 * tg;
            sfr[f].x += Prod[qq * 132 + qq - kk + 63];
            sfr[f].y += Prod[qq * 132 + qq - kk + 62];
            sfr[f].z += Prod[(qq + 8) * 132 + qq - kk + 71];
            sfr[f].w += Prod[(qq + 8) * 132 + qq - kk + 70];
        }
        {
            // p2c band uses the SAME index mapping: j = q0 - k0 + 449 + r
            int j = q0 - k0 + 449 + tid;
            j = j < 0 ? 0 : (j > 1023 ? 1023 : j);
            const uint4* bs = (const uint4*)(g_posqh + ((size_t)h * POSJ + j) * HD);
            uint4* bd = (uint4*)(Bandh + tid * 72);
#pragma unroll
            for (int i = 0; i < 8; i++) bd[i] = bs[i];
        }
        __syncthreads();

        // ---- P2C = K @ posQ_band^T -> Prod ----------------------------------
#pragma unroll
        for (int pass = 0; pass < 2; pass++) {
            float4 t[8];
#pragma unroll
            for (int f = 0; f < 8; f++) t[f] = make_float4(0.f, 0.f, 0.f, 0.f);
#pragma unroll
            for (int c = 0; c < 4; c++) {
                uint32_t a[4];
                const __half* kr = Ksh + qq * 72 + 16 * c + 2 * tg;
                a[0] = *(const uint32_t*)kr;
                a[1] = *(const uint32_t*)(kr + 8 * 72);
                a[2] = *(const uint32_t*)(kr + 8);
                a[3] = *(const uint32_t*)(kr + 8 * 72 + 8);
#pragma unroll
                for (int f = 0; f < 8; f++) {
                    uint32_t bb[2];
                    const __half* pb = Bandh + (64 * pass + 8 * f + g) * 72 + 16 * c + 2 * tg;
                    bb[0] = *(const uint32_t*)pb;
                    bb[1] = *(const uint32_t*)(pb + 8);
                    mma_f16(t[f], a, bb);
                }
            }
#pragma unroll
            for (int f = 0; f < 8; f++) {
                float* p0 = Prod + qq * 132 + 64 * pass + 8 * f + 2 * tg;
                p0[0] = t[f].x; p0[1] = t[f].y;
                p0[8 * 132] = t[f].z; p0[8 * 132 + 1] = t[f].w;
            }
        }
        __syncthreads();

        // ---- gather p2c (Prod[k][q-k+63]), scale + mask ---------------------
#pragma unroll
        for (int f = 0; f < 8; f++) {
            const int kk = 8 * f + 2 * tg;
            sfr[f].x += Prod[kk * 132 + qq - kk + 63];
            sfr[f].y += Prod[(kk + 1) * 132 + qq - kk + 62];
            sfr[f].z += Prod[kk * 132 + qq - kk + 71];
            sfr[f].w += Prod[(kk + 1) * 132 + qq - kk + 70];
            const float mk0 = Mf[k0 + kk], mk1 = Mf[k0 + kk + 1];
            sfr[f].x = sfr[f].x * SCORE_SCALE + mk0;
            sfr[f].y = sfr[f].y * SCORE_SCALE + mk1;
            sfr[f].z = sfr[f].z * SCORE_SCALE + mk0;
            sfr[f].w = sfr[f].w * SCORE_SCALE + mk1;
        }

        // ---- online softmax -------------------------------------------------
        float r0 = -1e30f, r1 = -1e30f;
#pragma unroll
        for (int f = 0; f < 8; f++) {
            r0 = fmaxf(r0, fmaxf(sfr[f].x, sfr[f].y));
            r1 = fmaxf(r1, fmaxf(sfr[f].z, sfr[f].w));
        }
        r0 = fmaxf(r0, __shfl_xor_sync(0xffffffffu, r0, 1));
        r0 = fmaxf(r0, __shfl_xor_sync(0xffffffffu, r0, 2));
        r1 = fmaxf(r1, __shfl_xor_sync(0xffffffffu, r1, 1));
        r1 = fmaxf(r1, __shfl_xor_sync(0xffffffffu, r1, 2));
        const float nm0 = fmaxf(m0, r0), nm1 = fmaxf(m1, r1);
        const float sc0 = __expf(m0 - nm0), sc1 = __expf(m1 - nm1);
        float rs0 = 0.f, rs1 = 0.f;
#pragma unroll
        for (int f = 0; f < 8; f++) {
            const float px = __expf(sfr[f].x - nm0);
            const float py = __expf(sfr[f].y - nm0);
            const float pz = __expf(sfr[f].z - nm1);
            const float pw = __expf(sfr[f].w - nm1);
            rs0 += px + py; rs1 += pz + pw;
            *(__half2*)(Ps + qq * 72 + 8 * f + 2 * tg) = __floats2half2_rn(px, py);
            *(__half2*)(Ps + (qq + 8) * 72 + 8 * f + 2 * tg) = __floats2half2_rn(pz, pw);
            acc[f].x *= sc0; acc[f].y *= sc0;
            acc[f].z *= sc1; acc[f].w *= sc1;
        }
        rs0 += __shfl_xor_sync(0xffffffffu, rs0, 1);
        rs0 += __shfl_xor_sync(0xffffffffu, rs0, 2);
        rs1 += __shfl_xor_sync(0xffffffffu, rs1, 1);
        rs1 += __shfl_xor_sync(0xffffffffu, rs1, 2);
        l0 = l0 * sc0 + rs0;
        l1 = l1 * sc1 + rs1;
        m0 = nm0; m1 = nm1;

        __syncwarp();   // Ps rows are warp-local; warp-level visibility suffices

        // ---- PV: acc += P @ V ----------------------------------------------
#pragma unroll
        for (int c = 0; c < 4; c++) {
            uint32_t a[4];
            const __half* pr = Ps + qq * 72 + 16 * c + 2 * tg;
            a[0] = *(const uint32_t*)pr;
            a[1] = *(const uint32_t*)(pr + 8 * 72);
            a[2] = *(const uint32_t*)(pr + 8);
            a[3] = *(const uint32_t*)(pr + 8 * 72 + 8);
#pragma unroll
            for (int f = 0; f < 8; f++) {
                uint32_t bb[2];
                const __half* vb = Vth + (8 * f + g) * 72 + 16 * c + 2 * tg;
                bb[0] = *(const uint32_t*)vb;
                bb[1] = *(const uint32_t*)(vb + 8);
                mma_f16(acc[f], a, bb);
            }
        }
    }

    // ---- epilogue: normalize, write [b, s, h*64+d] as f32 -------------------
    const float inv0 = 1.0f / l0, inv1 = 1.0f / l1;
    float* orow0 = out + ((size_t)b * S_LEN + q0 + qq) * DIM + h * HD;
    float* orow1 = orow0 + 8 * DIM;
#pragma unroll
    for (int f = 0; f < 8; f++) {
        const int col = 8 * f + 2 * tg;
        *(float2*)(orow0 + col) = make_float2(acc[f].x * inv0, acc[f].y * inv0);
        *(float2*)(orow1 + col) = make_float2(acc[f].z * inv1, acc[f].w * inv1);
    }
}

// ---------------------------------------------------------------------------
extern "C" void kernel_launch(void* const* d_in, const int* in_sizes, int n_in,
                              void* d_out, int out_size)
{
    const float* x    = (const float*)d_in[0];
    const float* rel  = (const float*)d_in[1];
    const float* mask = (const float*)d_in[2];
    const float* Wq   = (const float*)d_in[3];
    const float* bq   = (const float*)d_in[4];
    const float* Wk   = (const float*)d_in[5];
    const float* bk   = (const float*)d_in[6];
    const float* Wv   = (const float*)d_in[7];
    const float* bv   = (const float*)d_in[8];
    float* out = (float*)d_out;

    // merged fp16 projections: token (Q,K,V) and pos (posQ, posK)
    proj_f16<0><<<dim3(8, 32, 3), dim3(256)>>>(x, Wq, Wk, Wv, bq, bk, bv);
    proj_f16<1><<<dim3(8, 8, 2), dim3(256)>>>(rel, Wq, Wk, Wk, bq, bk, bk);

    // fused fp16 attention with in-tile c2p/p2c
    cudaFuncSetAttribute(attn2_kernel, cudaFuncAttributeMaxDynamicSharedMemorySize,
                         ATTN2_SMEM);
    attn2_kernel<<<dim3(8, BH), dim3(128), ATTN2_SMEM>>>(mask, out);
}